// round 15
// baseline (speedup 1.0000x reference)
#include <cuda_runtime.h>
#include <cuda_fp16.h>
#include <cstdint>

#define NROW 16384
#define NC   64
#define BM   128
#define BK   128
#define NIT  (NROW / BK)              /* 128 */

#define A_ROW_B 544                   /* 136 floats: 128 data + 8 pad */
#define B_ROW_B 272                   /* 136 halves: 128 data + 8 pad */
#define A_STG_B (BM * A_ROW_B)        /* 69632 */
#define B_STG_B (NC * B_ROW_B)        /* 17408 */
#define STG_B   (A_STG_B + B_STG_B)   /* 87040 */
#define MAIN_SMEM (2 * STG_B)         /* 174080 dynamic (+16KB static ws) */

__device__ __half g_Bh[(size_t)NC * NROW];   // (x@w)^T fp16, K-major, 2 MiB
__device__ unsigned int g_bar;               // monotonic cross-CTA barrier

// ---------------------------------------------------------------------------
__device__ __forceinline__ uint32_t smem_u32(const void* p) {
    uint32_t a;
    asm("{ .reg .u64 t; cvta.to.shared.u64 t, %1; cvt.u32.u64 %0, t; }" : "=r"(a) : "l"(p));
    return a;
}
__device__ __forceinline__ void cp_async16(uint32_t saddr, const void* g) {
    asm volatile("cp.async.cg.shared.global [%0], [%1], 16;" :: "r"(saddr), "l"(g));
}
__device__ __forceinline__ uint32_t pack_h2(float lo, float hi) {
    uint32_t r;
    asm("cvt.rn.f16x2.f32 %0, %1, %2;" : "=r"(r) : "f"(hi), "f"(lo));
    return r;
}
__device__ __forceinline__ void mma_f16(float c[4], uint32_t a0, uint32_t a1,
                                        uint32_t a2, uint32_t a3,
                                        uint32_t b0, uint32_t b1) {
    asm volatile(
        "mma.sync.aligned.m16n8k16.row.col.f32.f16.f16.f32 "
        "{%0,%1,%2,%3},{%4,%5,%6,%7},{%8,%9},{%0,%1,%2,%3};"
        : "+f"(c[0]), "+f"(c[1]), "+f"(c[2]), "+f"(c[3])
        : "r"(a0), "r"(a1), "r"(a2), "r"(a3), "r"(b0), "r"(b1));
}

// ---------------------------------------------------------------------------
// Single fused kernel. 128 CTAs x 128 threads, 1 CTA/SM, all co-resident.
// Phase 0: issue A prefetch (stages 0,1) -> DRAM busy immediately.
// Phase 1: CTA bid builds g_Bh k-rows [bid*128, bid*128+128)  (x@w, fp16^T).
// Phase 2: global barrier (monotonic ticket counter; graph-replay safe).
// Phase 3: B prefetch + round-14 mainloop (BK=128, 2 stages, wait_group 1).
// ---------------------------------------------------------------------------
__global__ void __launch_bounds__(128, 1) gcn_fused(const float* __restrict__ A,
                                                    const float* __restrict__ x,
                                                    const float* __restrict__ w,
                                                    float* __restrict__ out) {
    extern __shared__ char smem[];
    __shared__ float ws[NC * NC];          // 16 KB static, separate from stages
    const uint32_t smb = smem_u32(smem);

    const int t    = threadIdx.x;
    const int m0   = blockIdx.x * BM;      // also this CTA's B k-slice base
    const int warp = t >> 5, lane = t & 31;
    const int g    = lane >> 2;            // 0..7
    const int q    = lane & 3;             // 0..3

    // ---- per-thread cp.async load plan (identical to round 14) ----
    const int ar = t >> 5, as = t & 31;
    const int bn = t >> 4, bs = t & 15;
    const char* gA = (const char*)A + ((size_t)(m0 + ar) * NROW + (size_t)as * 4) * 4;
    const char* gB = (const char*)g_Bh + ((size_t)bn * NROW + (size_t)bs * 8) * 2;
    const uint32_t sAo = (uint32_t)(ar * A_ROW_B + as * 16);
    const uint32_t sBo = (uint32_t)(A_STG_B + bn * B_ROW_B + bs * 16);

    auto load_A = [&](int st) {
        const uint32_t sb = smb + st * STG_B;
        #pragma unroll
        for (int j = 0; j < 32; ++j)
            cp_async16(sb + sAo + j * 2176u, gA + (size_t)j * 262144);
        gA += BK * 4;
    };
    auto load_B = [&](int st) {
        const uint32_t sb = smb + st * STG_B;
        #pragma unroll
        for (int j = 0; j < 8; ++j)
            cp_async16(sb + sBo + j * 2176u, gB + (size_t)j * 262144);
        gB += BK * 2;
    };

    // ---- Phase 0: A prefetch first, so DRAM streams under phase 1 ----
    load_A(0);
    asm volatile("cp.async.commit_group;");   // G0 = A stage 0
    load_A(1);
    asm volatile("cp.async.commit_group;");   // G1 = A stage 1

    // ---- Phase 1: build B slice (same FLOP order as old xw_t -> same bits) ----
    {
        #pragma unroll
        for (int j = 0; j < 8; ++j)
            ((float4*)ws)[j * 128 + t] = ((const float4*)w)[j * 128 + t];
        __syncthreads();

        const float* xr = x + (size_t)(m0 + t) * NC;    // one k-row per thread
        float acc[NC];
        #pragma unroll
        for (int n = 0; n < NC; ++n) acc[n] = 0.f;
        #pragma unroll 4
        for (int c = 0; c < NC; ++c) {
            const float xv = __ldg(xr + c);
            #pragma unroll
            for (int n4 = 0; n4 < NC / 4; ++n4) {       // ws broadcast reads
                float4 wv = *(const float4*)&ws[c * NC + n4 * 4];
                acc[n4 * 4 + 0] += xv * wv.x;
                acc[n4 * 4 + 1] += xv * wv.y;
                acc[n4 * 4 + 2] += xv * wv.z;
                acc[n4 * 4 + 3] += xv * wv.w;
            }
        }
        #pragma unroll
        for (int n = 0; n < NC; ++n)                    // coalesced across t
            g_Bh[(size_t)n * NROW + m0 + t] = __float2half_rn(acc[n]);
    }

    // ---- Phase 2: global barrier (monotonic, graph-replay safe) ----
    __threadfence();
    __syncthreads();
    if (t == 0) {
        unsigned tk = atomicAdd(&g_bar, 1u);
        unsigned target = ((tk >> 7) + 1u) << 7;        // next multiple of 128
        unsigned v;
        do {
            asm volatile("ld.acquire.gpu.u32 %0, [%1];" : "=r"(v) : "l"(&g_bar));
            if (v < target) __nanosleep(64);
        } while (v < target);
    }
    __syncthreads();

    // ---- Phase 3: B prefetch, then round-14 mainloop ----
    load_B(0);
    asm volatile("cp.async.commit_group;");   // G2 = B stage 0
    load_B(1);
    asm volatile("cp.async.commit_group;");   // G3 = B stage 1

    float acc[2][8][4];
    #pragma unroll
    for (int i = 0; i < 2; ++i)
        #pragma unroll
        for (int j = 0; j < 8; ++j)
            #pragma unroll
            for (int c = 0; c < 4; ++c) acc[i][j][c] = 0.f;

    for (int it = 0; it < NIT; ++it) {
        // it=0: leaves only G3 pending -> A0,A1,B0 complete. Cadence as r14.
        asm volatile("cp.async.wait_group 1;");
        __syncthreads();

        const int st = it & 1;
        const float*  sA = (const float*)(smem + st * STG_B);
        const __half* sB = (const __half*)(smem + st * STG_B + A_STG_B);

        #pragma unroll
        for (int kt = 0; kt < 8; ++kt) {            // eight k16 tiles
            const int kb = kt * 16 + 2 * q;
            uint32_t b0[8], b1[8];
            #pragma unroll
            for (int j = 0; j < 8; ++j) {           // conflict-free
                const int n = j * 8 + g;
                b0[j] = *(const uint32_t*)&sB[n * 136 + kb];
                b1[j] = *(const uint32_t*)&sB[n * 136 + kb + 8];
            }
            #pragma unroll
            for (int i = 0; i < 2; ++i) {
                const int R = warp * 32 + i * 16;
                float2 p0 = *(const float2*)&sA[(R + g)     * 136 + kb];
                float2 p1 = *(const float2*)&sA[(R + g + 8) * 136 + kb];
                float2 p2 = *(const float2*)&sA[(R + g)     * 136 + kb + 8];
                float2 p3 = *(const float2*)&sA[(R + g + 8) * 136 + kb + 8];
                uint32_t a0 = pack_h2(p0.x, p0.y);
                uint32_t a1 = pack_h2(p1.x, p1.y);
                uint32_t a2 = pack_h2(p2.x, p2.y);
                uint32_t a3 = pack_h2(p3.x, p3.y);
                #pragma unroll
                for (int j = 0; j < 8; ++j)
                    mma_f16(acc[i][j], a0, a1, a2, a3, b0[j], b1[j]);
            }
        }

        __syncthreads();
        if (it + 2 < NIT) { load_A(st); load_B(st); }
        asm volatile("cp.async.commit_group;");     // empty group keeps cadence
    }

    // ---- epilogue: direct write to out ----
    #pragma unroll
    for (int i = 0; i < 2; ++i) {
        #pragma unroll
        for (int j = 0; j < 8; ++j) {
            const int row = m0 + warp * 32 + i * 16 + g;
            const int col = j * 8 + q * 2;
            *(float2*)(out + (size_t)row * NC + col)       = make_float2(acc[i][j][0], acc[i][j][1]);
            *(float2*)(out + (size_t)(row + 8) * NC + col) = make_float2(acc[i][j][2], acc[i][j][3]);
        }
    }
}

// ---------------------------------------------------------------------------
extern "C" void kernel_launch(void* const* d_in, const int* in_sizes, int n_in,
                              void* d_out, int out_size) {
    const float* x   = (const float*)d_in[0];   // [16384, 64]
    const float* adj = (const float*)d_in[1];   // [16384, 16384]
    const float* w   = (const float*)d_in[2];   // [64, 64]
    float* out = (float*)d_out;

    cudaFuncSetAttribute(gcn_fused, cudaFuncAttributeMaxDynamicSharedMemorySize, MAIN_SMEM);
    gcn_fused<<<NROW / BM, 128, MAIN_SMEM>>>(adj, x, w, out);
}